// round 13
// baseline (speedup 1.0000x reference)
#include <cuda_runtime.h>
#include <cstdint>

// Problem constants
#define CCH 64      // channels
#define NI  16      // irreps
#define NK2 120
#define NK1 8
#define NK0 4

#define NPAIR 136        // #(x<=y) pairs
#define RUN_TOTAL 888    // sum over pairs of padded run lengths Lp(y)=((16-y)+1)&~1
#define TAB_ULL   (RUN_TOTAL + NPAIR + NI)   // 1040 ull per channel
#define TAB_BYTES (TAB_ULL * 8)              // 8320 B (multiple of 16)
#define TILE_ATOMS 1024  // atoms per work item (4 per thread, 256 threads)

typedef unsigned long long ull;

// Scratch (__device__ globals; no allocation)
__device__ float g_Usym[RUN_TOTAL * NK2];   // symmetrized U2, padded runs
__device__ float g_U1s[NPAIR * NK1];        // symmetrized U1
__device__ ull   g_tab[CCH * TAB_ULL];      // per-channel packed dup'd tables:
                                            //   [0,888)    At (cubic)
                                            //   [888,1024) c1s
                                            //   [1024,1040) c0s
__device__ unsigned int g_item;             // work-queue counter (reset each launch)

__device__ __forceinline__ ull pack2(float lo, float hi) {
    ull r; asm("mov.b64 %0,{%1,%2};" : "=l"(r) : "f"(lo), "f"(hi)); return r;
}
__device__ __forceinline__ ull dup2(float v) { return pack2(v, v); }
__device__ __forceinline__ void unpack2(ull v, float& lo, float& hi) {
    asm("mov.b64 {%0,%1},%2;" : "=f"(lo), "=f"(hi) : "l"(v));
}
__device__ __forceinline__ ull fma2(ull a, ull b, ull c) {
    ull d; asm("fma.rn.f32x2 %0,%1,%2,%3;" : "=l"(d) : "l"(a), "l"(b), "l"(c)); return d;
}
__device__ __forceinline__ uint32_t smem_u32(const void* p) {
    uint32_t a;
    asm("{ .reg .u64 t; cvta.to.shared.u64 t, %1; cvt.u32.u64 %0, t; }" : "=r"(a) : "l"(p));
    return a;
}
__device__ __forceinline__ void mbar_init(uint32_t mbar, uint32_t cnt) {
    asm volatile("mbarrier.init.shared.b64 [%0], %1;" :: "r"(mbar), "r"(cnt) : "memory");
}
__device__ __forceinline__ void mbar_expect_tx(uint32_t mbar, uint32_t bytes) {
    asm volatile("mbarrier.arrive.expect_tx.shared.b64 _, [%0], %1;"
                 :: "r"(mbar), "r"(bytes) : "memory");
}
__device__ __forceinline__ void bulk_g2s(uint32_t dst_smem, const void* src, uint32_t bytes,
                                         uint32_t mbar) {
    asm volatile("cp.async.bulk.shared::cta.global.mbarrier::complete_tx::bytes "
                 "[%0], [%1], %2, [%3];"
                 :: "r"(dst_smem), "l"(src), "r"(bytes), "r"(mbar) : "memory");
}
__device__ __forceinline__ void mbar_wait(uint32_t mbar, uint32_t parity) {
    asm volatile(
        "{\n\t.reg .pred P;\n\t"
        "WL_%=:\n\t"
        "mbarrier.try_wait.parity.acquire.cta.shared::cta.b64 P, [%0], %1, 0x989680;\n\t"
        "@P bra.uni WD_%=;\n\t"
        "bra.uni WL_%=;\n\t"
        "WD_%=:\n\t}"
        :: "r"(mbar), "r"(parity) : "memory");
}

// Sum of U2 over DISTINCT index-permutations of the multiset {x,y,i}, at basis k.
__device__ __forceinline__ float sym_sum_U2(const float* __restrict__ U2,
                                            int x, int y, int i, int k) {
    int ta[6] = {x, x, y, y, i, i};
    int tb[6] = {y, i, x, i, x, y};
    int tc[6] = {i, y, i, x, y, x};
    int seen[6]; int ns = 0;
    float v = 0.f;
    #pragma unroll
    for (int q = 0; q < 6; q++) {
        int code = (ta[q] << 8) | (tb[q] << 4) | tc[q];
        bool dup = false;
        for (int s = 0; s < ns; s++) if (seen[s] == code) dup = true;
        if (!dup) {
            seen[ns++] = code;
            v += U2[(((ta[q] * NI + tb[q]) * NI) + tc[q]) * NK2 + k];
        }
    }
    return v;
}

// ---------------------------------------------------------------------------
// Kernel A: symmetrize U2 and U1 — one thread per OUTPUT element.
// ---------------------------------------------------------------------------
__global__ __launch_bounds__(256)
void sym_kernel(const float* __restrict__ U2,
                const float* __restrict__ U1) {
    const int idx = blockIdx.x * 256 + threadIdx.x;
    if (idx < RUN_TOTAL * NK2) {
        const int row = idx / NK2;
        const int k   = idx % NK2;
        int y = 0, base = 0, Lp = 0;
        for (;;) {
            Lp = ((NI - y) + 1) & ~1;
            int sz = (y + 1) * Lp;
            if (row < base + sz) break;
            base += sz; y++;
        }
        int rem = row - base;
        int x = rem / Lp;
        int j = rem - x * Lp;
        int i = (NI - Lp) + j;
        float v = (i >= y) ? sym_sum_U2(U2, x, y, i, k) : 0.f;
        g_Usym[row * NK2 + k] = v;
    } else {
        int idx2 = idx - RUN_TOTAL * NK2;
        if (idx2 < NPAIR * NK1) {
            int p = idx2 / NK1, k = idx2 - (idx2 / NK1) * NK1;
            int y = 0;
            while ((y + 1) * (y + 2) / 2 <= p) y++;
            int x = p - y * (y + 1) / 2;
            float v = U1[(x * NI + y) * NK1 + k];
            if (x != y) v += U1[(y * NI + x) * NK1 + k];
            g_U1s[idx2] = v;
        }
    }
}

// ---------------------------------------------------------------------------
// Kernel B: g_tab[c] = packed dup'd tables; work-counter reset.
// Blocks 0..55: At rows (GEMM). Block 56: c1s + c0s + counter.
// ---------------------------------------------------------------------------
__global__ __launch_bounds__(256)
void gemm_kernel(const float* __restrict__ w2,
                 const float* __restrict__ w1,
                 const float* __restrict__ w0,
                 const float* __restrict__ U0) {
    const int bid = blockIdx.x, tid = threadIdx.x;
    if (bid < 56) {
        __shared__ float sW[NK2 * CCH];      // 30 KB
        __shared__ float sU[16 * NK2];       // 7.5 KB
        const int r0 = bid * 16;
        for (int i = tid; i < NK2 * CCH; i += 256) sW[i] = w2[i];
        for (int i = tid; i < 16 * NK2; i += 256) {
            int rr = r0 + i / NK2;
            sU[i] = (rr < RUN_TOTAL) ? g_Usym[rr * NK2 + (i % NK2)] : 0.f;
        }
        __syncthreads();
        const int c = tid & 63;
        const int tr = tid >> 6;             // 0..3
        float acc[4] = {0.f, 0.f, 0.f, 0.f};
        #pragma unroll 4
        for (int k = 0; k < NK2; k++) {
            float wv = sW[k * CCH + c];
            #pragma unroll
            for (int q = 0; q < 4; q++)
                acc[q] += sU[(tr + 4 * q) * NK2 + k] * wv;
        }
        #pragma unroll
        for (int q = 0; q < 4; q++) {
            int row = r0 + tr + 4 * q;
            if (row < RUN_TOTAL) g_tab[(size_t)c * TAB_ULL + row] = dup2(acc[q]);
        }
    } else {
        for (int idx = tid; idx < CCH * NPAIR; idx += 256) {
            int c = idx & 63, p = idx >> 6;
            float s = 0.f;
            #pragma unroll
            for (int k = 0; k < NK1; k++) s += g_U1s[p * NK1 + k] * w1[k * CCH + c];
            g_tab[(size_t)c * TAB_ULL + RUN_TOTAL + p] = dup2(s);
        }
        for (int idx = tid; idx < CCH * NI; idx += 256) {
            int c = idx & 63, x = idx >> 6;
            float s = 0.f;
            #pragma unroll
            for (int k = 0; k < NK0; k++) s += U0[x * NK0 + k] * w0[k * CCH + c];
            g_tab[(size_t)c * TAB_ULL + RUN_TOTAL + NPAIR + x] = dup2(s);
        }
        if (tid == 0) g_item = 0u;           // reset work queue (every replay)
    }
}

// ---------------------------------------------------------------------------
// Contract kernel: persistent CTAs, double-buffered cp.async.bulk table
// prefetch (item k+1's table copied while computing item k). R7 compute core:
// 256 threads, 4 atoms/thread as two f32x2 pairs, Horner form:
//   out = sum_y f_y * ( c0_y + sum_{x<=y} f_x * (c1_xy + sum_i At_xyi f_i) )
// Copy protocol: every slot issue is a real copy (channel 0 if past end) so
// mbarrier phases are deterministic; both buffers drained before exit.
// ---------------------------------------------------------------------------
__global__ __launch_bounds__(256, 2)
void contract_kernel(const float* __restrict__ feats,
                     float* __restrict__ out,
                     int Natoms, int nItems) {
    const int tid = threadIdx.x;

    __shared__ __align__(16) ull sBuf[2][TAB_ULL];   // 2 x 8320 B
    __shared__ __align__(8) unsigned long long sMbarStore[2];
    __shared__ unsigned int sSlot[2];

    const uint32_t mb[2] = { smem_u32(&sMbarStore[0]), smem_u32(&sMbarStore[1]) };
    const uint32_t bufaddr[2] = { smem_u32(&sBuf[0][0]), smem_u32(&sBuf[1][0]) };

    if (tid == 0) {
        mbar_init(mb[0], 1);
        mbar_init(mb[1], 1);
        unsigned a = atomicAdd(&g_item, 1u);
        unsigned b = atomicAdd(&g_item, 1u);
        sSlot[0] = a; sSlot[1] = b;
        // fence: mbarrier init visible to async proxy before first copy
        asm volatile("fence.proxy.async.shared::cta;" ::: "memory");
        mbar_expect_tx(mb[0], TAB_BYTES);
        bulk_g2s(bufaddr[0], g_tab + (size_t)((a < (unsigned)nItems ? (a & 63) : 0)) * TAB_ULL,
                 TAB_BYTES, mb[0]);
        mbar_expect_tx(mb[1], TAB_BYTES);
        bulk_g2s(bufaddr[1], g_tab + (size_t)((b < (unsigned)nItems ? (b & 63) : 0)) * TAB_ULL,
                 TAB_BYTES, mb[1]);
    }
    __syncthreads();

    int buf = 0;
    int phase0 = 0, phase1 = 0;

    for (;;) {
        const unsigned cur = sSlot[buf];
        if (cur >= (unsigned)nItems) break;
        const int c    = cur & 63;   (void)c;
        const int tile = cur >> 6;

        // Start feature loads before waiting on the table copy (independent).
        const int base = tile * TILE_ATOMS + tid;
        const int n0 = base, n1 = base + 256, n2 = base + 512, n3 = base + 768;
        const bool v0 = n0 < Natoms, v1 = n1 < Natoms, v2 = n2 < Natoms, v3 = n3 < Natoms;
        const int ch = cur & 63;

        float4 fa[4], fb[4], fc[4], fd[4];
        {
            const float4* p0 = (const float4*)(feats + ((size_t)n0 * CCH + ch) * NI);
            const float4* p1 = (const float4*)(feats + ((size_t)n1 * CCH + ch) * NI);
            const float4* p2 = (const float4*)(feats + ((size_t)n2 * CCH + ch) * NI);
            const float4* p3 = (const float4*)(feats + ((size_t)n3 * CCH + ch) * NI);
            #pragma unroll
            for (int t = 0; t < 4; t++) {
                fa[t] = v0 ? p0[t] : make_float4(0.f, 0.f, 0.f, 0.f);
                fb[t] = v1 ? p1[t] : make_float4(0.f, 0.f, 0.f, 0.f);
                fc[t] = v2 ? p2[t] : make_float4(0.f, 0.f, 0.f, 0.f);
                fd[t] = v3 ? p3[t] : make_float4(0.f, 0.f, 0.f, 0.f);
            }
        }
        ull fp0[NI], fp1[NI];
        #pragma unroll
        for (int t = 0; t < 4; t++) {
            fp0[4 * t + 0] = pack2(fa[t].x, fb[t].x);
            fp0[4 * t + 1] = pack2(fa[t].y, fb[t].y);
            fp0[4 * t + 2] = pack2(fa[t].z, fb[t].z);
            fp0[4 * t + 3] = pack2(fa[t].w, fb[t].w);
            fp1[4 * t + 0] = pack2(fc[t].x, fd[t].x);
            fp1[4 * t + 1] = pack2(fc[t].y, fd[t].y);
            fp1[4 * t + 2] = pack2(fc[t].z, fd[t].z);
            fp1[4 * t + 3] = pack2(fc[t].w, fd[t].w);
        }

        // Wait for this buffer's table copy to land.
        if (buf == 0) { mbar_wait(mb[0], phase0); phase0 ^= 1; }
        else          { mbar_wait(mb[1], phase1); phase1 ^= 1; }

        const ull* sA  = sBuf[buf];
        const ull* sC1 = sBuf[buf] + RUN_TOTAL;
        const ull* sC0 = sBuf[buf] + RUN_TOTAL + NPAIR;

        ull acc0 = pack2(0.f, 0.f), acc1 = pack2(0.f, 0.f);

        int roff = 0, pp = 0;
        #pragma unroll
        for (int y = 0; y < NI; y++) {
            const int L  = NI - y;
            const int Lp = (L + 1) & ~1;
            const int i0 = NI - Lp;
            ull t0 = sC0[y];                  // c0 folded into t_y seed
            ull t1 = t0;
            #pragma unroll
            for (int x = 0; x <= y; x++) {
                ull s0 = sC1[pp];
                ull s1 = s0;
                const ulonglong2* r = (const ulonglong2*)(sA + roff);
                #pragma unroll
                for (int t = 0; t < Lp / 2; t++) {
                    ulonglong2 pv = r[t];
                    s0 = fma2(pv.x, fp0[i0 + 2 * t + 0], s0);
                    s0 = fma2(pv.y, fp0[i0 + 2 * t + 1], s0);
                    s1 = fma2(pv.x, fp1[i0 + 2 * t + 0], s1);
                    s1 = fma2(pv.y, fp1[i0 + 2 * t + 1], s1);
                }
                t0 = fma2(s0, fp0[x], t0);    // t_y += S * f_x
                t1 = fma2(s1, fp1[x], t1);
                roff += Lp; pp++;
            }
            acc0 = fma2(t0, fp0[y], acc0);    // out += t_y * f_y
            acc1 = fma2(t1, fp1[y], acc1);
        }

        float r0, r1, r2, r3;
        unpack2(acc0, r0, r1);
        unpack2(acc1, r2, r3);
        if (v0) out[(size_t)n0 * CCH + ch] = r0;
        if (v1) out[(size_t)n1 * CCH + ch] = r1;
        if (v2) out[(size_t)n2 * CCH + ch] = r2;
        if (v3) out[(size_t)n3 * CCH + ch] = r3;

        __syncthreads();   // everyone done reading sBuf[buf] & sSlot[buf]

        if (tid == 0) {
            unsigned nx = atomicAdd(&g_item, 1u);
            sSlot[buf] = nx;
            mbar_expect_tx(mb[buf], TAB_BYTES);
            bulk_g2s(bufaddr[buf],
                     g_tab + (size_t)((nx < (unsigned)nItems ? (nx & 63) : 0)) * TAB_ULL,
                     TAB_BYTES, mb[buf]);
        }
        buf ^= 1;
    }

    // Drain: one outstanding copy per buffer; complete before CTA exit.
    mbar_wait(mb[0], phase0);
    mbar_wait(mb[1], phase1);
}

extern "C" void kernel_launch(void* const* d_in, const int* in_sizes, int n_in,
                              void* d_out, int out_size) {
    const float* feats = (const float*)d_in[0];  // [N, C, I]
    const float* U2    = (const float*)d_in[1];  // [I, I, I, K2]
    const float* U1    = (const float*)d_in[2];  // [I, I, K1]
    const float* U0    = (const float*)d_in[3];  // [I, K0]
    const float* w2    = (const float*)d_in[4];  // [K2, C]
    const float* w1    = (const float*)d_in[5];  // [K1, C]
    const float* w0    = (const float*)d_in[6];  // [K0, C]
    float* out = (float*)d_out;                  // [N, C]

    const int Natoms = in_sizes[0] / (CCH * NI);
    const int nTiles = (Natoms + TILE_ATOMS - 1) / TILE_ATOMS;
    const int nItems = nTiles * CCH;

    const int symElems = RUN_TOTAL * NK2 + NPAIR * NK1;
    sym_kernel<<<(symElems + 255) / 256, 256>>>(U2, U1);
    gemm_kernel<<<57, 256>>>(w2, w1, w0, U0);

    contract_kernel<<<304, 256>>>(feats, out, Natoms, nItems);
}

// round 14
// speedup vs baseline: 1.5922x; 1.5922x over previous
#include <cuda_runtime.h>
#include <cstdint>

// Problem constants
#define CCH 64      // channels
#define NI  16      // irreps
#define NK2 120
#define NK1 8
#define NK0 4

#define NPAIR 136        // #(x<=y) pairs
#define RUN_TOTAL 888    // sum over pairs of padded run lengths Lp(y)=((16-y)+1)&~1
#define TAB_ULL   (RUN_TOTAL + NPAIR + NI)   // 1040 ull per channel
#define TILE_ATOMS 1024  // atoms per work item (4 per thread, 256 threads)

typedef unsigned long long ull;

// Scratch (__device__ globals; no allocation)
__device__ float g_Usym[RUN_TOTAL * NK2];   // symmetrized U2, padded runs
__device__ float g_U1s[NPAIR * NK1];        // symmetrized U1
__device__ ull   g_tab[CCH * TAB_ULL];      // per-channel packed dup'd tables:
                                            //   [0,888)     At (cubic)
                                            //   [888,1024)  c1s
                                            //   [1024,1040) c0s

__device__ __forceinline__ ull pack2(float lo, float hi) {
    ull r; asm("mov.b64 %0,{%1,%2};" : "=l"(r) : "f"(lo), "f"(hi)); return r;
}
__device__ __forceinline__ ull dup2(float v) { return pack2(v, v); }
__device__ __forceinline__ void unpack2(ull v, float& lo, float& hi) {
    asm("mov.b64 {%0,%1},%2;" : "=f"(lo), "=f"(hi) : "l"(v));
}
__device__ __forceinline__ ull fma2(ull a, ull b, ull c) {
    ull d; asm("fma.rn.f32x2 %0,%1,%2,%3;" : "=l"(d) : "l"(a), "l"(b), "l"(c)); return d;
}

// Sum of U2 over DISTINCT index-permutations of the multiset {x,y,i}, at basis k.
__device__ __forceinline__ float sym_sum_U2(const float* __restrict__ U2,
                                            int x, int y, int i, int k) {
    int ta[6] = {x, x, y, y, i, i};
    int tb[6] = {y, i, x, i, x, y};
    int tc[6] = {i, y, i, x, y, x};
    int seen[6]; int ns = 0;
    float v = 0.f;
    #pragma unroll
    for (int q = 0; q < 6; q++) {
        int code = (ta[q] << 8) | (tb[q] << 4) | tc[q];
        bool dup = false;
        for (int s = 0; s < ns; s++) if (seen[s] == code) dup = true;
        if (!dup) {
            seen[ns++] = code;
            v += U2[(((ta[q] * NI + tb[q]) * NI) + tc[q]) * NK2 + k];
        }
    }
    return v;
}

// ---------------------------------------------------------------------------
// Kernel A: symmetrize U2 and U1 — one thread per OUTPUT element.
// ---------------------------------------------------------------------------
__global__ __launch_bounds__(256)
void sym_kernel(const float* __restrict__ U2,
                const float* __restrict__ U1) {
    const int idx = blockIdx.x * 256 + threadIdx.x;
    if (idx < RUN_TOTAL * NK2) {
        const int row = idx / NK2;
        const int k   = idx % NK2;
        int y = 0, base = 0, Lp = 0;
        for (;;) {
            Lp = ((NI - y) + 1) & ~1;
            int sz = (y + 1) * Lp;
            if (row < base + sz) break;
            base += sz; y++;
        }
        int rem = row - base;
        int x = rem / Lp;
        int j = rem - x * Lp;
        int i = (NI - Lp) + j;
        float v = (i >= y) ? sym_sum_U2(U2, x, y, i, k) : 0.f;
        g_Usym[row * NK2 + k] = v;
    } else {
        int idx2 = idx - RUN_TOTAL * NK2;
        if (idx2 < NPAIR * NK1) {
            int p = idx2 / NK1, k = idx2 - (idx2 / NK1) * NK1;
            int y = 0;
            while ((y + 1) * (y + 2) / 2 <= p) y++;
            int x = p - y * (y + 1) / 2;
            float v = U1[(x * NI + y) * NK1 + k];
            if (x != y) v += U1[(y * NI + x) * NK1 + k];
            g_U1s[idx2] = v;
        }
    }
}

// ---------------------------------------------------------------------------
// Kernel B: g_tab[c] = packed dup'd tables (At via smem GEMM; c1s/c0s tiny).
// ---------------------------------------------------------------------------
__global__ __launch_bounds__(256)
void gemm_kernel(const float* __restrict__ w2,
                 const float* __restrict__ w1,
                 const float* __restrict__ w0,
                 const float* __restrict__ U0) {
    const int bid = blockIdx.x, tid = threadIdx.x;
    if (bid < 56) {
        __shared__ float sW[NK2 * CCH];      // 30 KB
        __shared__ float sU[16 * NK2];       // 7.5 KB
        const int r0 = bid * 16;
        for (int i = tid; i < NK2 * CCH; i += 256) sW[i] = w2[i];
        for (int i = tid; i < 16 * NK2; i += 256) {
            int rr = r0 + i / NK2;
            sU[i] = (rr < RUN_TOTAL) ? g_Usym[rr * NK2 + (i % NK2)] : 0.f;
        }
        __syncthreads();
        const int c = tid & 63;
        const int tr = tid >> 6;             // 0..3
        float acc[4] = {0.f, 0.f, 0.f, 0.f};
        #pragma unroll 4
        for (int k = 0; k < NK2; k++) {
            float wv = sW[k * CCH + c];
            #pragma unroll
            for (int q = 0; q < 4; q++)
                acc[q] += sU[(tr + 4 * q) * NK2 + k] * wv;
        }
        #pragma unroll
        for (int q = 0; q < 4; q++) {
            int row = r0 + tr + 4 * q;
            if (row < RUN_TOTAL) g_tab[(size_t)c * TAB_ULL + row] = dup2(acc[q]);
        }
    } else {
        for (int idx = tid; idx < CCH * NPAIR; idx += 256) {
            int c = idx & 63, p = idx >> 6;
            float s = 0.f;
            #pragma unroll
            for (int k = 0; k < NK1; k++) s += g_U1s[p * NK1 + k] * w1[k * CCH + c];
            g_tab[(size_t)c * TAB_ULL + RUN_TOTAL + p] = dup2(s);
        }
        for (int idx = tid; idx < CCH * NI; idx += 256) {
            int c = idx & 63, x = idx >> 6;
            float s = 0.f;
            #pragma unroll
            for (int k = 0; k < NK0; k++) s += U0[x * NK0 + k] * w0[k * CCH + c];
            g_tab[(size_t)c * TAB_ULL + RUN_TOTAL + NPAIR + x] = dup2(s);
        }
    }
}

// ---------------------------------------------------------------------------
// Contract kernel: STATIC channel-major chunking. 304 CTAs (152 SM x 2, all
// resident in one wave), each owns a contiguous range of items ordered so
// consecutive items share a channel -> table reload only on channel change
// (~2 per CTA instead of ~8.4). No atomics, no per-item publish barrier.
// R7 compute core: 256 threads, 4 atoms/thread as two f32x2 pairs, Horner:
//   out = sum_y f_y * ( c0_y + sum_{x<=y} f_x * (c1_xy + sum_i At_xyi f_i) )
// ---------------------------------------------------------------------------
__global__ __launch_bounds__(256, 2)
void contract_kernel(const float* __restrict__ feats,
                     float* __restrict__ out,
                     int Natoms, int nItems, int nTiles) {
    const int tid = threadIdx.x;

    __shared__ __align__(16) ull sTab[TAB_ULL];   // 8320 B packed dup'd tables

    // Static contiguous partition of [0, nItems)
    const int g = gridDim.x;
    const int q = nItems / g, r = nItems % g;
    const int b = blockIdx.x;
    int start, cnt;
    if (b < r) { cnt = q + 1; start = b * (q + 1); }
    else       { cnt = q;     start = r * (q + 1) + (b - r) * q; }

    const ull* sA  = sTab;
    const ull* sC1 = sTab + RUN_TOTAL;
    const ull* sC0 = sTab + RUN_TOTAL + NPAIR;

    int curC = -1;
    for (int it = 0; it < cnt; it++) {
        const int id   = start + it;
        const int c    = id / nTiles;          // channel-major ordering
        const int tile = id - c * nTiles;

        if (c != curC) {
            __syncthreads();                   // prior readers of sTab done
            const ulonglong2* src = (const ulonglong2*)(g_tab + (size_t)c * TAB_ULL);
            ulonglong2* dst = (ulonglong2*)sTab;
            for (int j = tid; j < TAB_ULL / 2; j += 256) dst[j] = src[j];
            __syncthreads();
            curC = c;
        }

        const int base = tile * TILE_ATOMS + tid;
        const int n0 = base, n1 = base + 256, n2 = base + 512, n3 = base + 768;
        const bool v0 = n0 < Natoms, v1 = n1 < Natoms, v2 = n2 < Natoms, v3 = n3 < Natoms;

        float4 fa[4], fb[4], fc[4], fd[4];
        {
            const float4* p0 = (const float4*)(feats + ((size_t)n0 * CCH + c) * NI);
            const float4* p1 = (const float4*)(feats + ((size_t)n1 * CCH + c) * NI);
            const float4* p2 = (const float4*)(feats + ((size_t)n2 * CCH + c) * NI);
            const float4* p3 = (const float4*)(feats + ((size_t)n3 * CCH + c) * NI);
            #pragma unroll
            for (int t = 0; t < 4; t++) {
                fa[t] = v0 ? p0[t] : make_float4(0.f, 0.f, 0.f, 0.f);
                fb[t] = v1 ? p1[t] : make_float4(0.f, 0.f, 0.f, 0.f);
                fc[t] = v2 ? p2[t] : make_float4(0.f, 0.f, 0.f, 0.f);
                fd[t] = v3 ? p3[t] : make_float4(0.f, 0.f, 0.f, 0.f);
            }
        }
        ull fp0[NI], fp1[NI];
        #pragma unroll
        for (int t = 0; t < 4; t++) {
            fp0[4 * t + 0] = pack2(fa[t].x, fb[t].x);
            fp0[4 * t + 1] = pack2(fa[t].y, fb[t].y);
            fp0[4 * t + 2] = pack2(fa[t].z, fb[t].z);
            fp0[4 * t + 3] = pack2(fa[t].w, fb[t].w);
            fp1[4 * t + 0] = pack2(fc[t].x, fd[t].x);
            fp1[4 * t + 1] = pack2(fc[t].y, fd[t].y);
            fp1[4 * t + 2] = pack2(fc[t].z, fd[t].z);
            fp1[4 * t + 3] = pack2(fc[t].w, fd[t].w);
        }

        ull acc0 = pack2(0.f, 0.f), acc1 = pack2(0.f, 0.f);

        int roff = 0, pp = 0;
        #pragma unroll
        for (int y = 0; y < NI; y++) {
            const int L  = NI - y;
            const int Lp = (L + 1) & ~1;
            const int i0 = NI - Lp;
            ull t0 = sC0[y];                  // c0 folded into t_y seed
            ull t1 = t0;
            #pragma unroll
            for (int x = 0; x <= y; x++) {
                ull s0 = sC1[pp];
                ull s1 = s0;
                const ulonglong2* rr = (const ulonglong2*)(sA + roff);
                #pragma unroll
                for (int t = 0; t < Lp / 2; t++) {
                    ulonglong2 pv = rr[t];
                    s0 = fma2(pv.x, fp0[i0 + 2 * t + 0], s0);
                    s0 = fma2(pv.y, fp0[i0 + 2 * t + 1], s0);
                    s1 = fma2(pv.x, fp1[i0 + 2 * t + 0], s1);
                    s1 = fma2(pv.y, fp1[i0 + 2 * t + 1], s1);
                }
                t0 = fma2(s0, fp0[x], t0);    // t_y += S * f_x
                t1 = fma2(s1, fp1[x], t1);
                roff += Lp; pp++;
            }
            acc0 = fma2(t0, fp0[y], acc0);    // out += t_y * f_y
            acc1 = fma2(t1, fp1[y], acc1);
        }

        float r0, r1, r2, r3;
        unpack2(acc0, r0, r1);
        unpack2(acc1, r2, r3);
        if (v0) out[(size_t)n0 * CCH + c] = r0;
        if (v1) out[(size_t)n1 * CCH + c] = r1;
        if (v2) out[(size_t)n2 * CCH + c] = r2;
        if (v3) out[(size_t)n3 * CCH + c] = r3;
    }
}

extern "C" void kernel_launch(void* const* d_in, const int* in_sizes, int n_in,
                              void* d_out, int out_size) {
    const float* feats = (const float*)d_in[0];  // [N, C, I]
    const float* U2    = (const float*)d_in[1];  // [I, I, I, K2]
    const float* U1    = (const float*)d_in[2];  // [I, I, K1]
    const float* U0    = (const float*)d_in[3];  // [I, K0]
    const float* w2    = (const float*)d_in[4];  // [K2, C]
    const float* w1    = (const float*)d_in[5];  // [K1, C]
    const float* w0    = (const float*)d_in[6];  // [K0, C]
    float* out = (float*)d_out;                  // [N, C]

    const int Natoms = in_sizes[0] / (CCH * NI);
    const int nTiles = (Natoms + TILE_ATOMS - 1) / TILE_ATOMS;
    const int nItems = nTiles * CCH;

    const int symElems = RUN_TOTAL * NK2 + NPAIR * NK1;
    sym_kernel<<<(symElems + 255) / 256, 256>>>(U2, U1);
    gemm_kernel<<<57, 256>>>(w2, w1, w0, U0);

    contract_kernel<<<304, 256>>>(feats, out, Natoms, nItems, nTiles);
}